// round 3
// baseline (speedup 1.0000x reference)
#include <cuda_runtime.h>
#include <math.h>

// Problem constants (fixed shapes)
#define BATCH 4
#define TLEN  1024
#define CH    512
#define DH    16
#define NROWS (BATCH*TLEN)   // 4096
#define OUTS  48             // k(16) | v(16) | r(16)
#define OCH   64

// Scratch (device globals). Transposed layout: [d][row]  (row = b*TLEN+t)
__device__ float g_kT[DH*NROWS];
__device__ float g_vT[DH*NROWS];
__device__ float g_rT[DH*NROWS];
__device__ float g_rwkvT[DH*NROWS];
__device__ float g_wsum[TLEN];

// packed f32x2 FMA (Blackwell): acc = a*b + acc  on two lanes
__device__ __forceinline__ void ffma2(unsigned long long& acc,
                                      unsigned long long a,
                                      unsigned long long b) {
    asm("fma.rn.f32x2 %0, %1, %2, %0;" : "+l"(acc) : "l"(a), "l"(b));
}

// ---------------------------------------------------------------------------
// Kernel 1: w_sum[u] = alpha[u] * sum_{d=0}^{T-1-u} time_w[T-1-d] * beta[u+d]
// One warp per u. 32 blocks x 1024 threads.
// ---------------------------------------------------------------------------
__global__ void wsum_kernel(const float* __restrict__ time_w,
                            const float* __restrict__ alpha,
                            const float* __restrict__ beta) {
    int tid  = threadIdx.x;
    int lane = tid & 31;
    int u    = blockIdx.x * 32 + (tid >> 5);
    float s = 0.f;
    int dmax = TLEN - 1 - u;
    for (int d = lane; d <= dmax; d += 32)
        s += time_w[TLEN - 1 - d] * beta[u + d];
    #pragma unroll
    for (int off = 16; off > 0; off >>= 1)
        s += __shfl_down_sync(0xFFFFFFFFu, s, off);
    if (lane == 0)
        g_wsum[u] = alpha[u] * s;
}

// ---------------------------------------------------------------------------
// Kernel 2: projections with f32x2 packed FMA.
//   block tile: 32 rows x 48 outs, K-chunk 64, 256 threads.
//   thread tile: 3 outs x 2 rows (packed in one f32x2 accumulator per out).
// Grid: 128 blocks.
// ---------------------------------------------------------------------------
#define KC 64
#define RPB 32

__global__ __launch_bounds__(256) void proj_kernel(
    const float* __restrict__ x,
    const float* __restrict__ Wk, const float* __restrict__ bk,
    const float* __restrict__ Wv, const float* __restrict__ bv,
    const float* __restrict__ Wr, const float* __restrict__ br)
{
    __shared__ float2 WsDup[KC][OUTS];   // weight duplicated into both lanes (24 KB)
    __shared__ float2 Xp[KC][RPB/2];     // row pairs (8 KB)

    int tid  = threadIdx.x;
    int row0 = blockIdx.x * RPB;

    int rx = tid & 15;        // row-pair index (rows 2rx, 2rx+1)
    int oy = tid >> 4;        // out group (3 outs each)
    int o0 = oy * 3;

    unsigned long long acc0 = 0ull, acc1 = 0ull, acc2 = 0ull;

    for (int kc = 0; kc < CH; kc += KC) {
        // weight tile: WsDup[kk][out] = {w, w}
        #pragma unroll
        for (int it = 0; it < (OUTS*KC)/256; it++) {
            int e   = tid + it * 256;
            int kk  = e & (KC - 1);
            int out = e >> 6;
            const float* wsrc = (out < 16) ? (Wk + out * CH)
                              : (out < 32) ? (Wv + (out - 16) * CH)
                                           : (Wr + (out - 32) * CH);
            float w = wsrc[kc + kk];
            WsDup[kk][out] = make_float2(w, w);
        }
        // x tile with time shift: Xp[kk][rp] = {xx[2rp][c], xx[2rp+1][c]}
        #pragma unroll
        for (int it = 0; it < (RPB/2*KC)/256; it++) {
            int e  = tid + it * 256;
            int kk = e & (KC - 1);
            int rp = e >> 6;
            int c  = kc + kk;
            float v0, v1;
            #pragma unroll
            for (int i = 0; i < 2; i++) {
                int row = row0 + rp * 2 + i;
                int t   = row & (TLEN - 1);
                float val;
                if (c < CH/2) val = (t > 0) ? x[(row - 1) * CH + c] : 0.f;
                else          val = x[row * CH + c];
                if (i == 0) v0 = val; else v1 = val;
            }
            Xp[kk][rp] = make_float2(v0, v1);
        }
        __syncthreads();

        #pragma unroll
        for (int kk = 0; kk < KC; kk++) {
            unsigned long long xv = *(const unsigned long long*)&Xp[kk][rx];
            unsigned long long w0 = *(const unsigned long long*)&WsDup[kk][o0 + 0];
            unsigned long long w1 = *(const unsigned long long*)&WsDup[kk][o0 + 1];
            unsigned long long w2 = *(const unsigned long long*)&WsDup[kk][o0 + 2];
            ffma2(acc0, w0, xv);
            ffma2(acc1, w1, xv);
            ffma2(acc2, w2, xv);
        }
        __syncthreads();
    }

    // epilogue: bias, exp-clip for k, write transposed (coalesced float2)
    unsigned long long accs[3] = {acc0, acc1, acc2};
    #pragma unroll
    for (int j = 0; j < 3; j++) {
        int out   = o0 + j;
        int d     = out & 15;
        int which = out >> 4;
        float2 a  = *(float2*)&accs[j];
        float bias = (which == 0) ? bk[d] : (which == 1) ? bv[d] : br[d];
        a.x += bias; a.y += bias;
        float* dst;
        if (which == 0) {
            a.x = expf(fminf(fmaxf(a.x, -60.f), 30.f));
            a.y = expf(fminf(fmaxf(a.y, -60.f), 30.f));
            dst = g_kT;
        } else if (which == 1) dst = g_vT;
        else                   dst = g_rT;
        *(float2*)&dst[d * NROWS + row0 + rx * 2] = a;
    }
}

// ---------------------------------------------------------------------------
// Kernel 3: per (b,d): cumsum of k over t, kv_mean, and fused
//   rwkv = r * wsum[t] * kv_mean / (cumsum_k + 1e-8)     (all coalesced)
// Grid: 64 blocks x 1024 threads. Deterministic.
// ---------------------------------------------------------------------------
__global__ __launch_bounds__(1024) void scan_kernel() {
    __shared__ float wsh[32];
    __shared__ float rsh[32];
    __shared__ float s_km;

    int bd = blockIdx.x;
    int b  = bd >> 4;
    int d  = bd & 15;
    int t  = threadIdx.x;
    int lane = t & 31;
    int wid  = t >> 5;

    int idxT = d * NROWS + (b << 10) + t;
    float kval = g_kT[idxT];
    float vval = g_vT[idxT];
    float rval = g_rT[idxT];
    float wst  = g_wsum[t];

    // inclusive block scan of k
    float val = kval;
    #pragma unroll
    for (int off = 1; off < 32; off <<= 1) {
        float n = __shfl_up_sync(0xFFFFFFFFu, val, off);
        if (lane >= off) val += n;
    }
    if (lane == 31) wsh[wid] = val;

    // kv reduction (independent shared array; one barrier serves both)
    float kv = kval * vval;
    #pragma unroll
    for (int off = 16; off > 0; off >>= 1)
        kv += __shfl_down_sync(0xFFFFFFFFu, kv, off);
    if (lane == 0) rsh[wid] = kv;
    __syncthreads();

    if (wid == 0) {
        float s = wsh[lane];
        #pragma unroll
        for (int off = 1; off < 32; off <<= 1) {
            float n = __shfl_up_sync(0xFFFFFFFFu, s, off);
            if (lane >= off) s += n;
        }
        wsh[lane] = s;

        float r = rsh[lane];
        #pragma unroll
        for (int off = 16; off > 0; off >>= 1)
            r += __shfl_down_sync(0xFFFFFFFFu, r, off);
        if (lane == 0) s_km = r * (1.0f / (float)TLEN);
    }
    __syncthreads();

    float sumk = val + ((wid > 0) ? wsh[wid - 1] : 0.f);
    float km   = s_km;
    g_rwkvT[idxT] = rval * wst * km * __fdividef(1.0f, sumk + 1e-8f);
}

// ---------------------------------------------------------------------------
// Kernel 4: out[b,t,o] = (sum_d rwkv[b,t,d]*Wo[o][d] + bo[o]) * gamma[t]
// 4 rows x 64 outs per block, 256 threads. Grid: 1024 blocks.
// ---------------------------------------------------------------------------
__global__ __launch_bounds__(256) void out_kernel(
    const float* __restrict__ Wo, const float* __restrict__ bo,
    const float* __restrict__ gamma, float* __restrict__ out)
{
    int tid = threadIdx.x;
    int o   = tid & 63;
    int rl  = tid >> 6;
    int row = blockIdx.x * 4 + rl;
    int t   = row & (TLEN - 1);

    const float4* wop = (const float4*)(Wo + o * DH);
    float4 w0 = wop[0], w1 = wop[1], w2 = wop[2], w3 = wop[3];
    float wor[16] = {w0.x,w0.y,w0.z,w0.w, w1.x,w1.y,w1.z,w1.w,
                     w2.x,w2.y,w2.z,w2.w, w3.x,w3.y,w3.z,w3.w};

    float rv[16];
    #pragma unroll
    for (int d = 0; d < 16; d++)
        rv[d] = __ldg(&g_rwkvT[d * NROWS + row]);   // uniform per row-group

    float acc = 0.f;
    #pragma unroll
    for (int d = 0; d < 16; d++)
        acc += rv[d] * wor[d];

    out[row * OCH + o] = (acc + bo[o]) * gamma[t];
}

// ---------------------------------------------------------------------------
extern "C" void kernel_launch(void* const* d_in, const int* in_sizes, int n_in,
                              void* d_out, int out_size)
{
    const float* x      = (const float*)d_in[0];
    const float* time_w = (const float*)d_in[1];
    const float* alpha  = (const float*)d_in[2];
    const float* beta   = (const float*)d_in[3];
    const float* gamma  = (const float*)d_in[4];
    const float* Wk     = (const float*)d_in[5];
    const float* bk     = (const float*)d_in[6];
    const float* Wv     = (const float*)d_in[7];
    const float* bv     = (const float*)d_in[8];
    const float* Wr     = (const float*)d_in[9];
    const float* br     = (const float*)d_in[10];
    const float* Wo     = (const float*)d_in[11];
    const float* bo     = (const float*)d_in[12];
    float* out = (float*)d_out;

    wsum_kernel<<<32, 1024>>>(time_w, alpha, beta);
    proj_kernel<<<NROWS / RPB, 256>>>(x, Wk, bk, Wv, bv, Wr, br);
    scan_kernel<<<BATCH * DH, 1024>>>();
    out_kernel<<<NROWS / 4, 256>>>(Wo, bo, gamma, out);
}

// round 5
// speedup vs baseline: 1.2168x; 1.2168x over previous
#include <cuda_runtime.h>
#include <math.h>

// Problem constants (fixed shapes)
#define BATCH 4
#define TLEN  1024
#define CH    512
#define DH    16
#define NROWS (BATCH*TLEN)   // 4096
#define OUTS  48             // k(16) | v(16) | r(16)
#define OCH   64
#define NSPLIT 4             // K-split factor for proj

typedef unsigned long long ull;

// Scratch (device globals)
__device__ float g_pk[NSPLIT*DH*NROWS];   // raw partial dot for k (pre-bias/exp)
__device__ float g_pv[NSPLIT*DH*NROWS];
__device__ float g_pr[NSPLIT*DH*NROWS];
__device__ float g_rwkvT[DH*NROWS];       // [d][row]
__device__ float g_wsum[TLEN];

__device__ __forceinline__ void ffma2(ull& acc, ull a, ull b) {
    asm("fma.rn.f32x2 %0, %1, %2, %0;" : "+l"(acc) : "l"(a), "l"(b));
}

// ---------------------------------------------------------------------------
// Kernel 1: w_sum[u] = alpha[u] * sum_{d=0}^{T-1-u} time_w[T-1-d] * beta[u+d]
// ---------------------------------------------------------------------------
__global__ void wsum_kernel(const float* __restrict__ time_w,
                            const float* __restrict__ alpha,
                            const float* __restrict__ beta) {
    int tid  = threadIdx.x;
    int lane = tid & 31;
    int u    = blockIdx.x * 32 + (tid >> 5);
    float s = 0.f;
    int dmax = TLEN - 1 - u;
    for (int d = lane; d <= dmax; d += 32)
        s += time_w[TLEN - 1 - d] * beta[u + d];
    #pragma unroll
    for (int off = 16; off > 0; off >>= 1)
        s += __shfl_down_sync(0xFFFFFFFFu, s, off);
    if (lane == 0)
        g_wsum[u] = alpha[u] * s;
}

// ---------------------------------------------------------------------------
// Kernel 2: projection partial GEMM.
//   grid = 32 row-tiles x 4 K-splits = 128 blocks, 128 threads.
//   Block: 128 rows x 48 outs x K=128 (two 64-wide K-subtiles).
//   Thread tile: 8 rows (4 row-pairs, f32x2) x 6 outs. 4 warps (1/SMSP).
//   Raw partial sums written to g_p* (bias/exp applied in scan_kernel).
// ---------------------------------------------------------------------------
#define RPB 128
#define KC  64

__global__ __launch_bounds__(128) void proj_kernel(
    const float* __restrict__ x,
    const float* __restrict__ Wk,
    const float* __restrict__ Wv,
    const float* __restrict__ Wr)
{
    __shared__ float  Ws[OUTS][KC + 1];   // ~12.5 KB, pad 65 (conflict-free)
    __shared__ float2 Xp[KC][RPB/2 + 1];  // ~33.3 KB, row = 65 8B-units

    int tid   = threadIdx.x;
    int bid   = blockIdx.x;
    int tile  = bid >> 2;          // 0..31
    int split = bid & 3;           // 0..3
    int row0  = tile * RPB;
    int kbase = split * (CH / NSPLIT);     // 0,128,256,384

    int rx = tid & 15;             // row-pair base (pairs rx, rx+16, rx+32, rx+48)
    int oy = tid >> 4;             // 0..7
    int o0 = oy * 6;

    ull acc[6][4];
    #pragma unroll
    for (int j = 0; j < 6; j++)
        #pragma unroll
        for (int i = 0; i < 4; i++) acc[j][i] = 0ull;

    bool shifted = (kbase < CH/2);   // whole 128-chunk is in first/second half

    for (int kt = 0; kt < (CH/NSPLIT)/KC; kt++) {
        int kc = kbase + kt * KC;

        // --- weights: Ws[out][kk]  (coalesced gmem, contiguous smem) ---
        #pragma unroll 4
        for (int it = 0; it < (OUTS*KC)/128; it++) {
            int e   = tid + it * 128;
            int kk  = e & (KC - 1);
            int out = e >> 6;
            const float* wsrc = (out < 16) ? (Wk + out * CH)
                              : (out < 32) ? (Wv + (out - 16) * CH)
                                           : (Wr + (out - 32) * CH);
            Ws[out][kk] = wsrc[kc + kk];
        }
        // --- x tile (with time shift): Xp[kk][rp] = {xx[2rp], xx[2rp+1]} ---
        #pragma unroll 4
        for (int it = 0; it < ((RPB/2)*KC)/128; it++) {
            int e  = tid + it * 128;
            int kk = e & (KC - 1);
            int rp = e >> 6;               // 0..63
            int c  = kc + kk;
            int row = row0 + rp * 2;       // even
            float v0, v1;
            if (shifted) {
                int t0 = row & (TLEN - 1);
                v0 = t0 ? x[(row - 1) * CH + c] : 0.f;
                v1 = x[row * CH + c];      // (row+1)-1 = row; row+1 never t==0 (odd)
            } else {
                v0 = x[row * CH + c];
                v1 = x[(row + 1) * CH + c];
            }
            Xp[kk][rp] = make_float2(v0, v1);
        }
        __syncthreads();

        #pragma unroll
        for (int kk = 0; kk < KC; kk++) {
            ull xv[4];
            #pragma unroll
            for (int i = 0; i < 4; i++)
                xv[i] = *(const ull*)&Xp[kk][rx + 16 * i];
            #pragma unroll
            for (int j = 0; j < 6; j++) {
                unsigned int wb = __float_as_uint(Ws[o0 + j][kk]);
                ull wp;
                asm("mov.b64 %0, {%1, %1};" : "=l"(wp) : "r"(wb));
                #pragma unroll
                for (int i = 0; i < 4; i++)
                    ffma2(acc[j][i], wp, xv[i]);
            }
        }
        __syncthreads();
    }

    // epilogue: write raw partials, transposed [split][d][row], coalesced float2
    #pragma unroll
    for (int j = 0; j < 6; j++) {
        int out   = o0 + j;
        int d     = out & 15;
        int which = out >> 4;
        float* dst = (which == 0) ? g_pk : (which == 1) ? g_pv : g_pr;
        dst += split * (DH * NROWS) + d * NROWS;
        #pragma unroll
        for (int i = 0; i < 4; i++) {
            float2 a = *(float2*)&acc[j][i];
            *(float2*)&dst[row0 + (rx + 16 * i) * 2] = a;
        }
    }
}

// ---------------------------------------------------------------------------
// Kernel 3: combine K-split partials + bias, exp-clip k; per (b,d):
//   cumsum of k over t, kv_mean, fused rwkv = r*wsum*km/(cumsum+1e-8)
// Grid: 64 blocks x 1024 threads. Deterministic.
// ---------------------------------------------------------------------------
__global__ __launch_bounds__(1024) void scan_kernel(
    const float* __restrict__ bk, const float* __restrict__ bv,
    const float* __restrict__ br)
{
    __shared__ float wsh[32];
    __shared__ float rsh[32];
    __shared__ float s_km;

    int bd = blockIdx.x;
    int b  = bd >> 4;
    int d  = bd & 15;
    int t  = threadIdx.x;
    int lane = t & 31;
    int wid  = t >> 5;

    int idxT = d * NROWS + (b << 10) + t;

    float ks = bk[d], vs = bv[d], rs = br[d];
    #pragma unroll
    for (int s = 0; s < NSPLIT; s++) {
        int off = s * (DH * NROWS) + idxT;
        ks += g_pk[off];
        vs += g_pv[off];
        rs += g_pr[off];
    }
    float kval = expf(fminf(fmaxf(ks, -60.f), 30.f));
    float vval = vs;
    float rval = rs;
    float wst  = g_wsum[t];

    // inclusive block scan of k
    float val = kval;
    #pragma unroll
    for (int off = 1; off < 32; off <<= 1) {
        float n = __shfl_up_sync(0xFFFFFFFFu, val, off);
        if (lane >= off) val += n;
    }
    if (lane == 31) wsh[wid] = val;

    // kv reduction
    float kv = kval * vval;
    #pragma unroll
    for (int off = 16; off > 0; off >>= 1)
        kv += __shfl_down_sync(0xFFFFFFFFu, kv, off);
    if (lane == 0) rsh[wid] = kv;
    __syncthreads();

    if (wid == 0) {
        float s = wsh[lane];
        #pragma unroll
        for (int off = 1; off < 32; off <<= 1) {
            float n = __shfl_up_sync(0xFFFFFFFFu, s, off);
            if (lane >= off) s += n;
        }
        wsh[lane] = s;

        float r = rsh[lane];
        #pragma unroll
        for (int off = 16; off > 0; off >>= 1)
            r += __shfl_down_sync(0xFFFFFFFFu, r, off);
        if (lane == 0) s_km = r * (1.0f / (float)TLEN);
    }
    __syncthreads();

    float sumk = val + ((wid > 0) ? wsh[wid - 1] : 0.f);
    g_rwkvT[idxT] = rval * wst * s_km * __fdividef(1.0f, sumk + 1e-8f);
}

// ---------------------------------------------------------------------------
// Kernel 4: out[b,t,o] = (sum_d rwkv[b,t,d]*Wo[o][d] + bo[o]) * gamma[t]
// 16 rows x 64 outs per block via smem-staged rwkv. Grid: 256 blocks.
// ---------------------------------------------------------------------------
__global__ __launch_bounds__(256) void out_kernel(
    const float* __restrict__ Wo, const float* __restrict__ bo,
    const float* __restrict__ gamma, float* __restrict__ out)
{
    __shared__ float sh[DH][17];

    int tid  = threadIdx.x;
    int row0 = blockIdx.x * 16;

    {   // stage rwkvT[16 d][16 rows] (coalesced per d)
        int d  = tid >> 4;
        int rr = tid & 15;
        sh[d][rr] = g_rwkvT[d * NROWS + row0 + rr];
    }
    __syncthreads();

    int o  = tid & 63;
    int rg = tid >> 6;      // 4 row-groups of 4 rows

    const float4* wop = (const float4*)(Wo + o * DH);
    float4 w0 = wop[0], w1 = wop[1], w2 = wop[2], w3 = wop[3];
    float wor[16] = {w0.x,w0.y,w0.z,w0.w, w1.x,w1.y,w1.z,w1.w,
                     w2.x,w2.y,w2.z,w2.w, w3.x,w3.y,w3.z,w3.w};
    float bov = bo[o];

    #pragma unroll
    for (int q = 0; q < 4; q++) {
        int rr  = rg * 4 + q;
        int row = row0 + rr;
        int t   = row & (TLEN - 1);
        float acc = 0.f;
        #pragma unroll
        for (int d = 0; d < DH; d++)
            acc += sh[d][rr] * wor[d];
        out[row * OCH + o] = (acc + bov) * gamma[t];
    }
}

// ---------------------------------------------------------------------------
extern "C" void kernel_launch(void* const* d_in, const int* in_sizes, int n_in,
                              void* d_out, int out_size)
{
    const float* x      = (const float*)d_in[0];
    const float* time_w = (const float*)d_in[1];
    const float* alpha  = (const float*)d_in[2];
    const float* beta   = (const float*)d_in[3];
    const float* gamma  = (const float*)d_in[4];
    const float* Wk     = (const float*)d_in[5];
    const float* bk     = (const float*)d_in[6];
    const float* Wv     = (const float*)d_in[7];
    const float* bv     = (const float*)d_in[8];
    const float* Wr     = (const float*)d_in[9];
    const float* br     = (const float*)d_in[10];
    const float* Wo     = (const float*)d_in[11];
    const float* bo     = (const float*)d_in[12];
    float* out = (float*)d_out;

    wsum_kernel<<<32, 1024>>>(time_w, alpha, beta);
    proj_kernel<<<(NROWS / RPB) * NSPLIT, 128>>>(x, Wk, Wv, Wr);
    scan_kernel<<<BATCH * DH, 1024>>>(bk, bv, br);
    out_kernel<<<NROWS / 16, 256>>>(Wo, bo, gamma, out);
}

// round 7
// speedup vs baseline: 1.3526x; 1.1115x over previous
#include <cuda_runtime.h>
#include <math.h>

// Problem constants (fixed shapes)
#define BATCH 4
#define TLEN  1024
#define CH    512
#define DH    16
#define NROWS (BATCH*TLEN)   // 4096
#define OUTS  48             // k(16) | v(16) | r(16)
#define OCH   64
#define NSPLIT 4             // K-split factor for proj

typedef unsigned long long ull;

// Scratch (device globals)
__device__ float g_pk[NSPLIT*DH*NROWS];   // raw partial dot for k (pre-bias/exp)
__device__ float g_pv[NSPLIT*DH*NROWS];
__device__ float g_pr[NSPLIT*DH*NROWS];
__device__ float g_rwkvT[DH*NROWS];       // [d][row]
__device__ float g_wsum[TLEN];

__device__ __forceinline__ void ffma2(ull& acc, ull a, ull b) {
    asm("fma.rn.f32x2 %0, %1, %2, %0;" : "+l"(acc) : "l"(a), "l"(b));
}

// ---------------------------------------------------------------------------
// Kernel 1 (fused): blocks 0..127 = projection partial GEMM,
//                   blocks 128..159 = w_sum.
// 128 threads per block.
//
// proj: 32 row-tiles x 4 K-splits. Block: 128 rows x 48 outs x K=128.
//       Thread tile: 8 rows (4 f32x2 pairs) x 6 outs. Raw partials out.
// wsum: block handles 32 u's; thread (u = tid&31, part = tid>>5) strides d by 4.
// ---------------------------------------------------------------------------
#define RPB 128
#define KC  64
#define PROJ_BLOCKS 128

__global__ __launch_bounds__(128) void proj_wsum_kernel(
    const float* __restrict__ x,
    const float* __restrict__ Wk,
    const float* __restrict__ Wv,
    const float* __restrict__ Wr,
    const float* __restrict__ time_w,
    const float* __restrict__ alpha,
    const float* __restrict__ beta)
{
    int bid = blockIdx.x;
    int tid = threadIdx.x;

    if (bid >= PROJ_BLOCKS) {
        // ---------------- wsum part ----------------
        __shared__ float red[4][33];
        int u_local = tid & 31;
        int part    = tid >> 5;              // 0..3
        int u       = (bid - PROJ_BLOCKS) * 32 + u_local;
        float s = 0.f;
        int dmax = TLEN - 1 - u;
        for (int d = part; d <= dmax; d += 4)
            s += time_w[TLEN - 1 - d] * beta[u + d];
        red[part][u_local] = s;
        __syncthreads();
        if (part == 0) {
            float tot = red[0][u_local] + red[1][u_local]
                      + red[2][u_local] + red[3][u_local];
            g_wsum[u] = alpha[u] * tot;
        }
        return;
    }

    // ---------------- proj part ----------------
    __shared__ float  Ws[OUTS][KC + 1];   // ~12.5 KB, conflict-free
    __shared__ float2 Xp[KC][RPB/2 + 1];  // ~33.3 KB, row stride 65*8B

    int tile  = bid >> 2;          // 0..31
    int split = bid & 3;           // 0..3
    int row0  = tile * RPB;
    int kbase = split * (CH / NSPLIT);     // 0,128,256,384

    int rx = tid & 15;             // row-pair base (pairs rx, rx+16, rx+32, rx+48)
    int oy = tid >> 4;             // 0..7
    int o0 = oy * 6;

    ull acc[6][4];
    #pragma unroll
    for (int j = 0; j < 6; j++)
        #pragma unroll
        for (int i = 0; i < 4; i++) acc[j][i] = 0ull;

    bool shifted = (kbase < CH/2);   // whole 128-chunk is in first/second half

    for (int kt = 0; kt < (CH/NSPLIT)/KC; kt++) {
        int kc = kbase + kt * KC;

        // weights: Ws[out][kk]  (coalesced gmem, contiguous smem)
        #pragma unroll 4
        for (int it = 0; it < (OUTS*KC)/128; it++) {
            int e   = tid + it * 128;
            int kk  = e & (KC - 1);
            int out = e >> 6;
            const float* wsrc = (out < 16) ? (Wk + out * CH)
                              : (out < 32) ? (Wv + (out - 16) * CH)
                                           : (Wr + (out - 32) * CH);
            Ws[out][kk] = wsrc[kc + kk];
        }
        // x tile (with time shift): Xp[kk][rp] = {xx[2rp], xx[2rp+1]}
        #pragma unroll 4
        for (int it = 0; it < ((RPB/2)*KC)/128; it++) {
            int e  = tid + it * 128;
            int kk = e & (KC - 1);
            int rp = e >> 6;               // 0..63
            int c  = kc + kk;
            int row = row0 + rp * 2;       // even
            float v0, v1;
            if (shifted) {
                int t0 = row & (TLEN - 1);
                v0 = t0 ? x[(row - 1) * CH + c] : 0.f;
                v1 = x[row * CH + c];      // odd rows never have t==0
            } else {
                v0 = x[row * CH + c];
                v1 = x[(row + 1) * CH + c];
            }
            Xp[kk][rp] = make_float2(v0, v1);
        }
        __syncthreads();

        #pragma unroll
        for (int kk = 0; kk < KC; kk++) {
            ull xv[4];
            #pragma unroll
            for (int i = 0; i < 4; i++)
                xv[i] = *(const ull*)&Xp[kk][rx + 16 * i];
            #pragma unroll
            for (int j = 0; j < 6; j++) {
                unsigned int wb = __float_as_uint(Ws[o0 + j][kk]);
                ull wp;
                asm("mov.b64 %0, {%1, %1};" : "=l"(wp) : "r"(wb));
                #pragma unroll
                for (int i = 0; i < 4; i++)
                    ffma2(acc[j][i], wp, xv[i]);
            }
        }
        __syncthreads();
    }

    // epilogue: raw partials, [split][d][row], coalesced float2
    #pragma unroll
    for (int j = 0; j < 6; j++) {
        int out   = o0 + j;
        int d     = out & 15;
        int which = out >> 4;
        float* dst = (which == 0) ? g_pk : (which == 1) ? g_pv : g_pr;
        dst += split * (DH * NROWS) + d * NROWS;
        #pragma unroll
        for (int i = 0; i < 4; i++) {
            float2 a = *(float2*)&acc[j][i];
            *(float2*)&dst[row0 + (rx + 16 * i) * 2] = a;
        }
    }
}

// ---------------------------------------------------------------------------
// Kernel 2: combine K-split partials + bias, exp-clip k; per (b,d):
//   cumsum of k over t, kv_mean, fused rwkv = r*wsum*km/(cumsum+1e-8)
// Grid: 64 blocks x 1024 threads. Deterministic.
// ---------------------------------------------------------------------------
__global__ __launch_bounds__(1024) void scan_kernel(
    const float* __restrict__ bk, const float* __restrict__ bv,
    const float* __restrict__ br)
{
    __shared__ float wsh[32];
    __shared__ float rsh[32];
    __shared__ float s_km;

    int bd = blockIdx.x;
    int b  = bd >> 4;
    int d  = bd & 15;
    int t  = threadIdx.x;
    int lane = t & 31;
    int wid  = t >> 5;

    int idxT = d * NROWS + (b << 10) + t;

    float ks = bk[d], vs = bv[d], rs = br[d];
    #pragma unroll
    for (int s = 0; s < NSPLIT; s++) {
        int off = s * (DH * NROWS) + idxT;
        ks += g_pk[off];
        vs += g_pv[off];
        rs += g_pr[off];
    }
    float kval = expf(fminf(fmaxf(ks, -60.f), 30.f));
    float vval = vs;
    float rval = rs;
    float wst  = g_wsum[t];

    // inclusive block scan of k
    float val = kval;
    #pragma unroll
    for (int off = 1; off < 32; off <<= 1) {
        float n = __shfl_up_sync(0xFFFFFFFFu, val, off);
        if (lane >= off) val += n;
    }
    if (lane == 31) wsh[wid] = val;

    // kv reduction
    float kv = kval * vval;
    #pragma unroll
    for (int off = 16; off > 0; off >>= 1)
        kv += __shfl_down_sync(0xFFFFFFFFu, kv, off);
    if (lane == 0) rsh[wid] = kv;
    __syncthreads();

    if (wid == 0) {
        float s = wsh[lane];
        #pragma unroll
        for (int off = 1; off < 32; off <<= 1) {
            float n = __shfl_up_sync(0xFFFFFFFFu, s, off);
            if (lane >= off) s += n;
        }
        wsh[lane] = s;

        float r = rsh[lane];
        #pragma unroll
        for (int off = 16; off > 0; off >>= 1)
            r += __shfl_down_sync(0xFFFFFFFFu, r, off);
        if (lane == 0) s_km = r * (1.0f / (float)TLEN);
    }
    __syncthreads();

    float sumk = val + ((wid > 0) ? wsh[wid - 1] : 0.f);
    g_rwkvT[idxT] = rval * wst * s_km * __fdividef(1.0f, sumk + 1e-8f);
}

// ---------------------------------------------------------------------------
// Kernel 3: out[b,t,o] = (sum_d rwkv[b,t,d]*Wo[o][d] + bo[o]) * gamma[t]
// 512 blocks x 128 threads, 8 rows/block, no barrier.
// rwkvT loads are warp-uniform (broadcast, 1 sector) and L2-resident.
// ---------------------------------------------------------------------------
__global__ __launch_bounds__(128) void out_kernel(
    const float* __restrict__ Wo, const float* __restrict__ bo,
    const float* __restrict__ gamma, float* __restrict__ out)
{
    int tid  = threadIdx.x;
    int o    = tid & 63;
    int half = tid >> 6;                 // 0..1
    int row0 = blockIdx.x * 8 + half * 4;

    const float4* wop = (const float4*)(Wo + o * DH);
    float4 w0 = wop[0], w1 = wop[1], w2 = wop[2], w3 = wop[3];
    float wor[16] = {w0.x,w0.y,w0.z,w0.w, w1.x,w1.y,w1.z,w1.w,
                     w2.x,w2.y,w2.z,w2.w, w3.x,w3.y,w3.z,w3.w};
    float bov = bo[o];

    #pragma unroll
    for (int q = 0; q < 4; q++) {
        int row = row0 + q;
        int t   = row & (TLEN - 1);
        float acc = 0.f;
        #pragma unroll
        for (int d = 0; d < DH; d++)
            acc += __ldg(&g_rwkvT[d * NROWS + row]) * wor[d];
        out[row * OCH + o] = (acc + bov) * gamma[t];
    }
}

// ---------------------------------------------------------------------------
extern "C" void kernel_launch(void* const* d_in, const int* in_sizes, int n_in,
                              void* d_out, int out_size)
{
    const float* x      = (const float*)d_in[0];
    const float* time_w = (const float*)d_in[1];
    const float* alpha  = (const float*)d_in[2];
    const float* beta   = (const float*)d_in[3];
    const float* gamma  = (const float*)d_in[4];
    const float* Wk     = (const float*)d_in[5];
    const float* bk     = (const float*)d_in[6];
    const float* Wv     = (const float*)d_in[7];
    const float* bv     = (const float*)d_in[8];
    const float* Wr     = (const float*)d_in[9];
    const float* br     = (const float*)d_in[10];
    const float* Wo     = (const float*)d_in[11];
    const float* bo     = (const float*)d_in[12];
    float* out = (float*)d_out;

    // blocks 0..127: proj tiles;  blocks 128..159: wsum (32 u each)
    proj_wsum_kernel<<<PROJ_BLOCKS + TLEN/32, 128>>>(
        x, Wk, Wv, Wr, time_w, alpha, beta);
    scan_kernel<<<BATCH * DH, 1024>>>(bk, bv, br);
    out_kernel<<<NROWS / 8, 128>>>(Wo, bo, gamma, out);
}

// round 8
// speedup vs baseline: 2.3850x; 1.7633x over previous
#include <cuda_runtime.h>
#include <math.h>

// Problem constants (fixed shapes)
#define BATCH 4
#define TLEN  1024
#define CH    512
#define DH    16
#define NROWS (BATCH*TLEN)   // 4096
#define OUTS  48             // k(16) | v(16) | r(16)
#define OCH   64
#define NSPL  8              // effective K-splits (4 block-splits x 2 halves)
#define NBLOCKS 148
#define NTHREADS 256

typedef unsigned long long ull;
typedef unsigned int uint;

// Scratch (device globals)
__device__ float g_pk[NSPL*DH*NROWS];
__device__ float g_pv[NSPL*DH*NROWS];
__device__ float g_pr[NSPL*DH*NROWS];
__device__ float g_rwkvT[DH*NROWS];       // [d][row]
__device__ float g_wsum[TLEN];
__device__ unsigned int g_barcnt[2];      // monotonic barrier counters

__device__ __forceinline__ void ffma2(ull& acc, ull a, ull b) {
    asm("fma.rn.f32x2 %0, %1, %2, %0;" : "+l"(acc) : "l"(a), "l"(b));
}
__device__ __forceinline__ ull dup2(uint w) {
    ull r; asm("mov.b64 %0, {%1, %1};" : "=l"(r) : "r"(w)); return r;
}

// Replay-safe grid barrier (monotonic counter, wrap-safe compare).
__device__ __forceinline__ void grid_barrier(int id) {
    __syncthreads();
    if (threadIdx.x == 0) {
        __threadfence();
        unsigned int ticket = atomicAdd(&g_barcnt[id], 1u);
        unsigned int target = (ticket / NBLOCKS + 1u) * NBLOCKS;
        volatile unsigned int* p = &g_barcnt[id];
        while ((int)(*p - target) < 0) { }
        __threadfence();
    }
    __syncthreads();
}

// Shared memory (46080 B, overlaid across phases)
struct ProjSmem {
    float  Ws[2][32][50];     // [half][kk][out+pad]   12800 B
    float2 Xp[2][32][65];     // [half][kk][pair+pad]  33280 B
};
struct ScanSmem { float wsh[8]; float rsh[8]; float km; };

__global__ __launch_bounds__(NTHREADS) void rwkv_persistent(
    const float* __restrict__ x,
    const float* __restrict__ time_w,
    const float* __restrict__ alpha,
    const float* __restrict__ beta,
    const float* __restrict__ gamma,
    const float* __restrict__ Wk, const float* __restrict__ bk,
    const float* __restrict__ Wv, const float* __restrict__ bv,
    const float* __restrict__ Wr, const float* __restrict__ br,
    const float* __restrict__ Wo, const float* __restrict__ bo,
    float* __restrict__ out)
{
    __shared__ __align__(16) char s_raw[sizeof(ProjSmem)];
    int bid = blockIdx.x;
    int tid = threadIdx.x;

    // ======================= PHASE A =======================
    if (bid < 128) {
        // ---- projection partial GEMM ----
        ProjSmem* S = (ProjSmem*)s_raw;
        int tile  = bid >> 2;            // 0..31
        int split = bid & 3;             // 0..3
        int row0  = tile * 128;
        int half  = tid >> 7;            // 0..1 : K sub-chunk
        int ht    = tid & 127;
        int rx    = ht & 15;             // pairs rx, rx+16, rx+32, rx+48
        int oy    = ht >> 4;             // 0..7
        int o0    = oy * 6;
        int kbaseh = split * 128 + half * 64;
        bool shifted = (kbaseh < CH/2);  // 32-chunks never straddle 256

        ull acc[6][4];
        #pragma unroll
        for (int j = 0; j < 6; j++)
            #pragma unroll
            for (int i = 0; i < 4; i++) acc[j][i] = 0ull;

        for (int kt = 0; kt < 2; kt++) {
            int kc = kbaseh + kt * 32;

            // stage weights: Ws[half][kk][out]
            #pragma unroll
            for (int it = 0; it < (48*32)/128; it++) {
                int e   = ht + it * 128;
                int kk  = e & 31;
                int o   = e >> 5;       // 0..47
                const float* wsrc = (o < 16) ? (Wk + o * CH)
                                  : (o < 32) ? (Wv + (o - 16) * CH)
                                             : (Wr + (o - 32) * CH);
                S->Ws[half][kk][o] = wsrc[kc + kk];
            }
            // stage x pairs with time shift: Xp[half][kk][rp]
            #pragma unroll
            for (int it = 0; it < (64*32)/128; it++) {
                int e  = ht + it * 128;
                int kk = e & 31;
                int rp = e >> 5;        // 0..63
                int c  = kc + kk;
                int row = row0 + rp * 2;
                float v0, v1;
                if (shifted) {
                    int t0 = row & (TLEN - 1);
                    v0 = t0 ? x[(row - 1) * CH + c] : 0.f;
                    v1 = x[row * CH + c];
                } else {
                    v0 = x[row * CH + c];
                    v1 = x[(row + 1) * CH + c];
                }
                S->Xp[half][kk][rp] = make_float2(v0, v1);
            }
            __syncthreads();

            #pragma unroll 8
            for (int kk = 0; kk < 32; kk++) {
                ull xv[4];
                #pragma unroll
                for (int i = 0; i < 4; i++)
                    xv[i] = *(const ull*)&S->Xp[half][kk][rx + 16 * i];
                uint2 w01 = *(const uint2*)&S->Ws[half][kk][o0];
                uint2 w23 = *(const uint2*)&S->Ws[half][kk][o0 + 2];
                uint2 w45 = *(const uint2*)&S->Ws[half][kk][o0 + 4];
                ull wp[6];
                wp[0] = dup2(w01.x); wp[1] = dup2(w01.y);
                wp[2] = dup2(w23.x); wp[3] = dup2(w23.y);
                wp[4] = dup2(w45.x); wp[5] = dup2(w45.y);
                #pragma unroll
                for (int j = 0; j < 6; j++)
                    #pragma unroll
                    for (int i = 0; i < 4; i++)
                        ffma2(acc[j][i], wp[j], xv[i]);
            }
            __syncthreads();
        }

        // epilogue: raw partials [s][d][row], s = split*2+half
        int s = split * 2 + half;
        #pragma unroll
        for (int j = 0; j < 6; j++) {
            int o     = o0 + j;
            int d     = o & 15;
            int which = o >> 4;
            float* dst = (which == 0) ? g_pk : (which == 1) ? g_pv : g_pr;
            dst += (s * DH + d) * NROWS;
            #pragma unroll
            for (int i = 0; i < 4; i++) {
                float2 a = *(float2*)&acc[j][i];
                *(float2*)&dst[row0 + (rx + 16 * i) * 2] = a;
            }
        }
    } else {
        // ---- wsum on blocks 128..147 ----
        int base  = (bid - 128) * 52;
        int count = min(52, TLEN - base);
        int wid   = tid >> 5;
        int lane  = tid & 31;
        for (int ui = wid; ui < count; ui += 8) {
            int u = base + ui;
            float s = 0.f;
            int dmax = TLEN - 1 - u;
            for (int d = lane; d <= dmax; d += 32)
                s += time_w[TLEN - 1 - d] * beta[u + d];
            #pragma unroll
            for (int off = 16; off > 0; off >>= 1)
                s += __shfl_down_sync(0xFFFFFFFFu, s, off);
            if (lane == 0) g_wsum[u] = alpha[u] * s;
        }
    }

    grid_barrier(0);

    // ======================= PHASE B : scan (blocks 0..63) =======================
    if (bid < BATCH * DH) {
        ScanSmem* S = (ScanSmem*)s_raw;
        int b = bid >> 4;
        int d = bid & 15;
        int lane = tid & 31;
        int wid  = tid >> 5;
        int t0   = tid * 4;
        int base = d * NROWS + (b << 10) + t0;

        float4 ks = make_float4(0.f, 0.f, 0.f, 0.f);
        float4 vs = ks, rs = ks;
        #pragma unroll
        for (int s = 0; s < NSPL; s++) {
            int off = s * (DH * NROWS) + base;
            float4 a = *(const float4*)&g_pk[off];
            float4 c = *(const float4*)&g_pv[off];
            float4 e = *(const float4*)&g_pr[off];
            ks.x += a.x; ks.y += a.y; ks.z += a.z; ks.w += a.w;
            vs.x += c.x; vs.y += c.y; vs.z += c.z; vs.w += c.w;
            rs.x += e.x; rs.y += e.y; rs.z += e.z; rs.w += e.w;
        }
        float bkd = bk[d], bvd = bv[d], brd = br[d];
        float k0 = expf(fminf(fmaxf(ks.x + bkd, -60.f), 30.f));
        float k1 = expf(fminf(fmaxf(ks.y + bkd, -60.f), 30.f));
        float k2 = expf(fminf(fmaxf(ks.z + bkd, -60.f), 30.f));
        float k3 = expf(fminf(fmaxf(ks.w + bkd, -60.f), 30.f));
        float v0 = vs.x + bvd, v1 = vs.y + bvd, v2 = vs.z + bvd, v3 = vs.w + bvd;
        float r0 = rs.x + brd, r1 = rs.y + brd, r2 = rs.z + brd, r3 = rs.w + brd;

        // local inclusive prefix
        float p0 = k0, p1 = p0 + k1, p2 = p1 + k2, p3 = p2 + k3;
        float tot = p3;
        // warp inclusive scan of tot
        float sc = tot;
        #pragma unroll
        for (int off = 1; off < 32; off <<= 1) {
            float n = __shfl_up_sync(0xFFFFFFFFu, sc, off);
            if (lane >= off) sc += n;
        }
        if (lane == 31) S->wsh[wid] = sc;
        // kv reduction
        float kvs = k0*v0 + k1*v1 + k2*v2 + k3*v3;
        #pragma unroll
        for (int off = 16; off > 0; off >>= 1)
            kvs += __shfl_down_sync(0xFFFFFFFFu, kvs, off);
        if (lane == 0) S->rsh[wid] = kvs;
        __syncthreads();
        if (tid == 0) {
            float run = 0.f, kmacc = 0.f;
            #pragma unroll
            for (int w = 0; w < 8; w++) {
                float t = S->wsh[w]; S->wsh[w] = run; run += t;
                kmacc += S->rsh[w];
            }
            S->km = kmacc * (1.0f / (float)TLEN);
        }
        __syncthreads();
        float blk_excl = S->wsh[wid] + (sc - tot);
        float km = S->km;
        float4 wst = *(const float4*)&g_wsum[t0];

        float c0 = blk_excl + p0, c1 = blk_excl + p1,
              c2 = blk_excl + p2, c3 = blk_excl + p3;
        float4 o4;
        o4.x = r0 * wst.x * km * __fdividef(1.0f, c0 + 1e-8f);
        o4.y = r1 * wst.y * km * __fdividef(1.0f, c1 + 1e-8f);
        o4.z = r2 * wst.z * km * __fdividef(1.0f, c2 + 1e-8f);
        o4.w = r3 * wst.w * km * __fdividef(1.0f, c3 + 1e-8f);
        *(float4*)&g_rwkvT[base] = o4;
    }

    grid_barrier(1);

    // ======================= PHASE C : output GEMM =======================
    {
        int o  = tid & 63;
        int rl = tid >> 6;              // 0..3
        const float4* wop = (const float4*)(Wo + o * DH);
        float4 w0 = wop[0], w1 = wop[1], w2 = wop[2], w3 = wop[3];
        float wor[16] = {w0.x,w0.y,w0.z,w0.w, w1.x,w1.y,w1.z,w1.w,
                         w2.x,w2.y,w2.z,w2.w, w3.x,w3.y,w3.z,w3.w};
        float bov = bo[o];

        for (int g = bid; g < NROWS / 4; g += NBLOCKS) {
            int row = g * 4 + rl;
            int t   = row & (TLEN - 1);
            float acc = 0.f;
            #pragma unroll
            for (int d = 0; d < DH; d++)
                acc += __ldg(&g_rwkvT[d * NROWS + row]) * wor[d];
            out[row * OCH + o] = (acc + bov) * gamma[t];
        }
    }
}

// ---------------------------------------------------------------------------
extern "C" void kernel_launch(void* const* d_in, const int* in_sizes, int n_in,
                              void* d_out, int out_size)
{
    const float* x      = (const float*)d_in[0];
    const float* time_w = (const float*)d_in[1];
    const float* alpha  = (const float*)d_in[2];
    const float* beta   = (const float*)d_in[3];
    const float* gamma  = (const float*)d_in[4];
    const float* Wk     = (const float*)d_in[5];
    const float* bk     = (const float*)d_in[6];
    const float* Wv     = (const float*)d_in[7];
    const float* bv     = (const float*)d_in[8];
    const float* Wr     = (const float*)d_in[9];
    const float* br     = (const float*)d_in[10];
    const float* Wo     = (const float*)d_in[11];
    const float* bo     = (const float*)d_in[12];
    float* out = (float*)d_out;

    rwkv_persistent<<<NBLOCKS, NTHREADS>>>(
        x, time_w, alpha, beta, gamma,
        Wk, bk, Wv, bv, Wr, br, Wo, bo, out);
}